// round 4
// baseline (speedup 1.0000x reference)
#include <cuda_runtime.h>
#include <cuda_fp16.h>
#include <cstdint>

// Problem constants
#define BB 4
#define CC 3
#define HH 384
#define WW 384
#define KK 5
#define K2 25
#define HWSZ (HH * WW)          // 147456
#define NUM_ITER 20
#define INVZ2 44.4444444444444444f   // 1 / 0.15^2

// ---------------- precompute tile ----------------
#define PTX 32
#define PTY 16
#define PLX (PTX + 4)
#define PLY (PTY + 4)

// ---------------- iter tile: 64x8 pixels, 32x8 threads (2 px/thread) ------
#define TXV 32
#define TYV 8
#define PW  64                  // pixel width of tile
#define RLX (PW + 4)            // 68 floats per smem row (even -> float2 aligned)
#define RLY (TYV + 4)           // 12 rows

// Scratch:
//  g_w2 : 12 half2 planes per batch (taps 0..23 paired per pixel) -> 28.3 MB
//  g_w1 : 1 half plane per batch (tap 24)                         ->  1.2 MB
//  g_x  : ping-pong x buffers (fp32)
__device__ __half2 g_w2[(size_t)BB * 12 * HWSZ];
__device__ __half  g_w1[(size_t)BB * HWSZ];
__device__ float   g_x[2][(size_t)BB * HWSZ];

// ---------------------------------------------------------------------------
// Kernel 1: normalized bilateral weights -> fp16, x0 = feat * mask.
// img shifted by +10 BEFORE zero padding (matches reference): OOB taps use
// padded value 0 and their affinity underflows to exactly 0.
// ---------------------------------------------------------------------------
__global__ void __launch_bounds__(512) precompute_kernel(
    const float* __restrict__ img,
    const float* __restrict__ feat,
    const float* __restrict__ mask,
    float* __restrict__ x0)
{
    __shared__ float s[PLY][PLX][CC];

    const int b  = blockIdx.z;
    const int h0 = blockIdx.y * PTY;
    const int w0 = blockIdx.x * PTX;
    const int tx = threadIdx.x, ty = threadIdx.y;
    const int tid = ty * PTX + tx;

    const float* imb = img + (size_t)b * CC * HWSZ;

    for (int i = tid; i < PLY * PLX; i += PTX * PTY) {
        int ly = i / PLX, lx = i - ly * PLX;
        int gh = h0 + ly - 2, gw = w0 + lx - 2;
        bool ok = (gh >= 0) && (gh < HH) && (gw >= 0) && (gw < WW);
        #pragma unroll
        for (int c = 0; c < CC; c++)
            s[ly][lx][c] = ok ? imb[(size_t)c * HWSZ + gh * WW + gw] + 10.0f : 0.0f;
    }
    __syncthreads();

    const float c0 = s[ty + 2][tx + 2][0];
    const float c1 = s[ty + 2][tx + 2][1];
    const float c2 = s[ty + 2][tx + 2][2];

    float aff[K2];
    float sum = 0.0f;
    #pragma unroll
    for (int k = 0; k < K2; k++) {
        const int dy = k / KK, dx = k % KK;
        float d0 = s[ty + dy][tx + dx][0] - c0;
        float d1 = s[ty + dy][tx + dx][1] - c1;
        float d2 = s[ty + dy][tx + dx][2] - c2;
        float d  = d0 * d0 + d1 * d1 + d2 * d2;
        float a  = __expf(-d * INVZ2);
        aff[k] = a;
        sum += a;
    }
    const float inv = 1.0f / (sum + 1e-10f);

    const int gh = h0 + ty, gw = w0 + tx;
    const size_t pix = (size_t)gh * WW + gw;

    __half2* w2 = g_w2 + (size_t)b * 12 * HWSZ + pix;
    #pragma unroll
    for (int j = 0; j < 12; j++)
        w2[(size_t)j * HWSZ] = __floats2half2_rn(aff[2 * j] * inv, aff[2 * j + 1] * inv);
    g_w1[(size_t)b * HWSZ + pix] = __float2half_rn(aff[24] * inv);

    const size_t p = (size_t)b * HWSZ + pix;
    x0[p] = feat[p] * mask[p];
}

// ---------------------------------------------------------------------------
// Kernel 2: one propagation step, 2 adjacent pixels per thread, in-kernel
// renormalization (acc/ws) so fp16 weight error doesn't compound.
// 256-thread blocks: leaves ptxas ~64 regs so all 13 weight float2 loads stay
// register-resident and front-batched (MLP=13, spill-free).
// ---------------------------------------------------------------------------
__global__ void __launch_bounds__(256) iter_kernel(
    const float* __restrict__ mask,
    const float* __restrict__ xin_base,
    float* __restrict__ xout_base)
{
    __shared__ float s[RLY][RLX];   // 12 x 68 floats

    const int b  = blockIdx.z;
    const int h0 = blockIdx.y * TYV;
    const int w0 = blockIdx.x * PW;
    const int tx = threadIdx.x, ty = threadIdx.y;
    const int tid = ty * TXV + tx;

    const float* xin = xin_base + (size_t)b * HWSZ;

    // Load x tile + halo (region [h0-2, h0+10) x [w0-2, w0+66))
    for (int i = tid; i < RLY * RLX; i += TXV * TYV) {
        int ly = i / RLX, lx = i - ly * RLX;
        int gh = h0 + ly - 2, gw = w0 + lx - 2;
        bool ok = (gh >= 0) && (gh < HH) && (gw >= 0) && (gw < WW);
        s[ly][lx] = ok ? xin[gh * WW + gw] : 0.0f;
    }

    const int gh  = h0 + ty;
    const int wc  = w0 + 2 * tx;                  // even -> aligned vector loads
    const size_t pix = (size_t)gh * WW + wc;

    // Front-batched preload of all weight planes for both pixels
    const __half2* wbase = g_w2 + (size_t)b * 12 * HWSZ + pix;
    float2 Wj[12];
    #pragma unroll
    for (int j = 0; j < 12; j++)
        Wj[j] = *reinterpret_cast<const float2*>(wbase + (size_t)j * HWSZ);
    const __half2 w24 = *reinterpret_cast<const __half2*>(g_w1 + (size_t)b * HWSZ + pix);
    const float2 m = *reinterpret_cast<const float2*>(mask + (size_t)b * HWSZ + pix);

    __syncthreads();

    float acc0 = 0.f, ws0 = 0.f, acc1 = 0.f, ws1 = 0.f;

    #pragma unroll
    for (int dy = 0; dy < KK; dy++) {
        // 6 contiguous taps covering both pixels' 5-tap row: float2 indices
        // tx, tx+1, tx+2 (conflict-free LDS.64)
        const float2* r = reinterpret_cast<const float2*>(&s[ty + dy][0]) + tx;
        float2 va = r[0], vb = r[1], vc = r[2];
        float v0 = va.x, v1 = va.y, v2 = vb.x, v3 = vb.y, v4 = vc.x, v5 = vc.y;
        float vA[5] = { v0, v1, v2, v3, v4 };
        float vB[5] = { v1, v2, v3, v4, v5 };

        #pragma unroll
        for (int dx = 0; dx < KK; dx++) {
            const int k = dy * KK + dx;
            float wA, wB;
            if (k < 24) {
                const int j = k >> 1;
                __half2 hA = *reinterpret_cast<const __half2*>(&Wj[j].x);
                __half2 hB = *reinterpret_cast<const __half2*>(&Wj[j].y);
                if (k & 1) { wA = __high2float(hA); wB = __high2float(hB); }
                else       { wA = __low2float(hA);  wB = __low2float(hB);  }
            } else {
                wA = __low2float(w24);
                wB = __high2float(w24);
            }
            acc0 += wA * vA[dx]; ws0 += wA;
            acc1 += wB * vB[dx]; ws1 += wB;
        }
    }

    float2 res;
    res.x = __fdividef(acc0, ws0) * m.x;
    res.y = __fdividef(acc1, ws1) * m.y;

    *reinterpret_cast<float2*>(xout_base + (size_t)b * HWSZ + pix) = res;
}

// ---------------------------------------------------------------------------
extern "C" void kernel_launch(void* const* d_in, const int* in_sizes, int n_in,
                              void* d_out, int out_size)
{
    const float* img  = (const float*)d_in[0];
    const float* feat = (const float*)d_in[1];
    const float* mask = (const float*)d_in[2];
    float* out = (float*)d_out;

    // Resolve ping-pong scratch addresses (query only — no allocation)
    void* xsym = nullptr;
    cudaGetSymbolAddress(&xsym, g_x);
    float* x0 = (float*)xsym;
    float* x1 = x0 + (size_t)BB * HWSZ;

    dim3 pblk(PTX, PTY);
    dim3 pgrd(WW / PTX, HH / PTY, BB);    // (12, 24, 4)
    precompute_kernel<<<pgrd, pblk>>>(img, feat, mask, x0);

    dim3 iblk(TXV, TYV);
    dim3 igrd(WW / PW, HH / TYV, BB);     // (6, 48, 4) = 1152 blocks
    for (int i = 0; i < NUM_ITER; i++) {
        const float* src = (i & 1) ? x1 : x0;
        float* dst = (i == NUM_ITER - 1) ? out : ((i & 1) ? x0 : x1);
        iter_kernel<<<igrd, iblk>>>(mask, src, dst);
    }
}

// round 5
// speedup vs baseline: 1.1076x; 1.1076x over previous
#include <cuda_runtime.h>
#include <cuda_fp16.h>
#include <cstdint>

// Problem constants
#define BB 4
#define CC 3
#define HH 384
#define WW 384
#define KK 5
#define K2 25
#define HWSZ (HH * WW)          // 147456
#define NUM_ITER 20
#define INVZ2 44.4444444444444444f   // 1 / 0.15^2

// ---------------- precompute tile ----------------
#define PTX 32
#define PTY 16
#define PLX (PTX + 4)
#define PLY (PTY + 4)

// ---------------- iter tile: 64x16 pixels, 32x16 threads (2 px/thread) ----
#define TXV 32
#define TYV 16
#define PW  64                  // pixel width of tile
#define RLX (PW + 4)            // 68 floats per smem row (even -> float2 aligned)
#define RLY (TYV + 4)           // 20 rows

// Scratch:
//  g_w2 : 12 half2 planes per batch (taps 0..23 paired per pixel) -> 28.3 MB
//  g_w1 : 1 half plane per batch (tap 24)                         ->  1.2 MB
//  g_c  : 1 fp32 plane per batch: renorm factor 1/sum(quantized)  ->  2.4 MB
//  g_x  : ping-pong x buffers (fp32)
__device__ __half2 g_w2[(size_t)BB * 12 * HWSZ];
__device__ __half  g_w1[(size_t)BB * HWSZ];
__device__ float   g_c [(size_t)BB * HWSZ];
__device__ float   g_x[2][(size_t)BB * HWSZ];

// ---------------------------------------------------------------------------
// Kernel 1: normalized bilateral weights -> fp16, plus fp32 renorm factor
// c = 1 / sum(dequantized fp16 weights), and x0 = feat * mask.
// img shifted by +10 BEFORE zero padding (matches reference): OOB taps use
// padded value 0 and their affinity underflows to exactly 0.
// ---------------------------------------------------------------------------
__global__ void __launch_bounds__(512) precompute_kernel(
    const float* __restrict__ img,
    const float* __restrict__ feat,
    const float* __restrict__ mask,
    float* __restrict__ x0)
{
    __shared__ float s[PLY][PLX][CC];

    const int b  = blockIdx.z;
    const int h0 = blockIdx.y * PTY;
    const int w0 = blockIdx.x * PTX;
    const int tx = threadIdx.x, ty = threadIdx.y;
    const int tid = ty * PTX + tx;

    const float* imb = img + (size_t)b * CC * HWSZ;

    for (int i = tid; i < PLY * PLX; i += PTX * PTY) {
        int ly = i / PLX, lx = i - ly * PLX;
        int gh = h0 + ly - 2, gw = w0 + lx - 2;
        bool ok = (gh >= 0) && (gh < HH) && (gw >= 0) && (gw < WW);
        #pragma unroll
        for (int c = 0; c < CC; c++)
            s[ly][lx][c] = ok ? imb[(size_t)c * HWSZ + gh * WW + gw] + 10.0f : 0.0f;
    }
    __syncthreads();

    const float c0 = s[ty + 2][tx + 2][0];
    const float c1 = s[ty + 2][tx + 2][1];
    const float c2 = s[ty + 2][tx + 2][2];

    float aff[K2];
    float sum = 0.0f;
    #pragma unroll
    for (int k = 0; k < K2; k++) {
        const int dy = k / KK, dx = k % KK;
        float d0 = s[ty + dy][tx + dx][0] - c0;
        float d1 = s[ty + dy][tx + dx][1] - c1;
        float d2 = s[ty + dy][tx + dx][2] - c2;
        float d  = d0 * d0 + d1 * d1 + d2 * d2;
        float a  = __expf(-d * INVZ2);
        aff[k] = a;
        sum += a;
    }
    const float inv = 1.0f / (sum + 1e-10f);

    // Quantize to fp16, then compute the exact fp32 sum of the quantized
    // weights; its reciprocal is the per-pixel renorm factor.
    __half q[K2];
    float qs = 0.0f;
    #pragma unroll
    for (int k = 0; k < K2; k++) {
        q[k] = __float2half_rn(aff[k] * inv);
        qs += __half2float(q[k]);
    }
    const float cfac = 1.0f / qs;   // qs >= center weight ~ 1, no div-by-0

    const int gh = h0 + ty, gw = w0 + tx;
    const size_t pix = (size_t)gh * WW + gw;

    __half2* w2 = g_w2 + (size_t)b * 12 * HWSZ + pix;
    #pragma unroll
    for (int j = 0; j < 12; j++)
        w2[(size_t)j * HWSZ] = __halves2half2(q[2 * j], q[2 * j + 1]);
    g_w1[(size_t)b * HWSZ + pix] = q[24];
    g_c [(size_t)b * HWSZ + pix] = cfac;

    const size_t p = (size_t)b * HWSZ + pix;
    x0[p] = feat[p] * mask[p];
}

// ---------------------------------------------------------------------------
// Kernel 2: one propagation step, 2 adjacent pixels per thread.
//   x_out = mask * c * sum_k q_k * x_in[off_k]
// c is the precomputed 1/sum(q) -> exact averaging, no runtime ws sum/divide.
// ---------------------------------------------------------------------------
__global__ void __launch_bounds__(512) iter_kernel(
    const float* __restrict__ mask,
    const float* __restrict__ xin_base,
    float* __restrict__ xout_base)
{
    __shared__ float s[RLY][RLX];   // 20 x 68 floats

    const int b  = blockIdx.z;
    const int h0 = blockIdx.y * TYV;
    const int w0 = blockIdx.x * PW;
    const int tx = threadIdx.x, ty = threadIdx.y;
    const int tid = ty * TXV + tx;

    const float* xin = xin_base + (size_t)b * HWSZ;

    // Load x tile + halo (region [h0-2, h0+18) x [w0-2, w0+66))
    for (int i = tid; i < RLY * RLX; i += TXV * TYV) {
        int ly = i / RLX, lx = i - ly * RLX;
        int gh = h0 + ly - 2, gw = w0 + lx - 2;
        bool ok = (gh >= 0) && (gh < HH) && (gw >= 0) && (gw < WW);
        s[ly][lx] = ok ? xin[gh * WW + gw] : 0.0f;
    }
    __syncthreads();

    const int gh  = h0 + ty;
    const int wc  = w0 + 2 * tx;                  // even -> aligned vector loads
    const size_t pix = (size_t)gh * WW + wc;

    // Preload all weight planes for both pixels (float2 = 2 x half2)
    const __half2* wbase = g_w2 + (size_t)b * 12 * HWSZ + pix;
    float2 Wj[12];
    #pragma unroll
    for (int j = 0; j < 12; j++)
        Wj[j] = *reinterpret_cast<const float2*>(wbase + (size_t)j * HWSZ);
    const __half2 w24 = *reinterpret_cast<const __half2*>(g_w1 + (size_t)b * HWSZ + pix);
    const float2 cf   = *reinterpret_cast<const float2*>(g_c  + (size_t)b * HWSZ + pix);

    float acc0 = 0.f, acc1 = 0.f;

    #pragma unroll
    for (int dy = 0; dy < KK; dy++) {
        // 6 contiguous taps covering both pixels' 5-tap row: float2 indices
        // tx, tx+1, tx+2 (conflict-free LDS.64)
        const float2* r = reinterpret_cast<const float2*>(&s[ty + dy][0]) + tx;
        float2 va = r[0], vb = r[1], vc = r[2];
        float v[6] = { va.x, va.y, vb.x, vb.y, vc.x, vc.y };

        #pragma unroll
        for (int dx = 0; dx < KK; dx++) {
            const int k = dy * KK + dx;
            float wA, wB;
            if (k < 24) {
                const int j = k >> 1;
                __half2 hA = *reinterpret_cast<const __half2*>(&Wj[j].x);
                __half2 hB = *reinterpret_cast<const __half2*>(&Wj[j].y);
                if (k & 1) { wA = __high2float(hA); wB = __high2float(hB); }
                else       { wA = __low2float(hA);  wB = __low2float(hB);  }
            } else {
                wA = __low2float(w24);
                wB = __high2float(w24);
            }
            acc0 += wA * v[dx];
            acc1 += wB * v[dx + 1];
        }
    }

    const float2 m = *reinterpret_cast<const float2*>(mask + (size_t)b * HWSZ + pix);
    float2 res;
    res.x = acc0 * cf.x * m.x;
    res.y = acc1 * cf.y * m.y;

    *reinterpret_cast<float2*>(xout_base + (size_t)b * HWSZ + pix) = res;
}

// ---------------------------------------------------------------------------
extern "C" void kernel_launch(void* const* d_in, const int* in_sizes, int n_in,
                              void* d_out, int out_size)
{
    const float* img  = (const float*)d_in[0];
    const float* feat = (const float*)d_in[1];
    const float* mask = (const float*)d_in[2];
    float* out = (float*)d_out;

    void* xsym = nullptr;
    cudaGetSymbolAddress(&xsym, g_x);
    float* x0 = (float*)xsym;
    float* x1 = x0 + (size_t)BB * HWSZ;

    dim3 pblk(PTX, PTY);
    dim3 pgrd(WW / PTX, HH / PTY, BB);    // (12, 24, 4)
    precompute_kernel<<<pgrd, pblk>>>(img, feat, mask, x0);

    dim3 iblk(TXV, TYV);
    dim3 igrd(WW / PW, HH / TYV, BB);     // (6, 24, 4) = 576 blocks
    for (int i = 0; i < NUM_ITER; i++) {
        const float* src = (i & 1) ? x1 : x0;
        float* dst = (i == NUM_ITER - 1) ? out : ((i & 1) ? x0 : x1);
        iter_kernel<<<igrd, iblk>>>(mask, src, dst);
    }
}